// round 14
// baseline (speedup 1.0000x reference)
#include <cuda_runtime.h>
#include <cuda_fp16.h>
#include <math.h>
#include <stdint.h>

#define B_  4
#define S_  2048
#define D_  1024
#define H_  16
#define DK_ 64
#define LDQKV 3072                           // row stride of fused QKV output

// fp16 scratch (allocation-free rule: __device__ globals)
__device__ __half g_Xh[(size_t)B_ * S_ * D_];
__device__ __half g_Wh[(size_t)4 * D_ * D_];   // WQ|WK|WV|WO contiguous
__device__ __half g_QKVh[(size_t)B_ * S_ * LDQKV];
__device__ __half g_Ah[(size_t)B_ * S_ * D_];

// ---------------------------------------------------------------------------
// fp32 -> fp16 convert, 8 elems/thread.
// ---------------------------------------------------------------------------
__global__ void cvt_f16_k(const float4* __restrict__ in,
                          uint4* __restrict__ out, int n8)
{
    int i = blockIdx.x * blockDim.x + threadIdx.x;
    if (i < n8) {
        float4 a = in[2 * i];
        float4 b = in[2 * i + 1];
        __half2 h0 = __floats2half2_rn(a.x, a.y);
        __half2 h1 = __floats2half2_rn(a.z, a.w);
        __half2 h2 = __floats2half2_rn(b.x, b.y);
        __half2 h3 = __floats2half2_rn(b.z, b.w);
        uint4 u;
        u.x = *(uint32_t*)&h0; u.y = *(uint32_t*)&h1;
        u.z = *(uint32_t*)&h2; u.w = *(uint32_t*)&h3;
        out[i] = u;
    }
}

// ---------------------------------------------------------------------------
// mma / ldmatrix helpers
// ---------------------------------------------------------------------------
__device__ __forceinline__ void cp16(uint32_t dst_smem, const void* src) {
    asm volatile("cp.async.cg.shared.global [%0], [%1], 16;\n"
                 :: "r"(dst_smem), "l"(src));
}

__device__ __forceinline__ void mma_f16(float c[4], const uint32_t a[4],
                                        uint32_t b0, uint32_t b1) {
    asm volatile(
        "mma.sync.aligned.m16n8k16.row.col.f32.f16.f16.f32 "
        "{%0,%1,%2,%3}, {%4,%5,%6,%7}, {%8,%9}, {%0,%1,%2,%3};\n"
        : "+f"(c[0]), "+f"(c[1]), "+f"(c[2]), "+f"(c[3])
        : "r"(a[0]), "r"(a[1]), "r"(a[2]), "r"(a[3]), "r"(b0), "r"(b1));
}

__device__ __forceinline__ void ldsm4(uint32_t* r, uint32_t addr) {
    asm volatile("ldmatrix.sync.aligned.m8n8.x4.shared.b16 "
                 "{%0,%1,%2,%3}, [%4];"
                 : "=r"(r[0]), "=r"(r[1]), "=r"(r[2]), "=r"(r[3]) : "r"(addr));
}

__device__ __forceinline__ void ldsm4t(uint32_t* r, uint32_t addr) {
    asm volatile("ldmatrix.sync.aligned.m8n8.x4.trans.shared.b16 "
                 "{%0,%1,%2,%3}, [%4];"
                 : "=r"(r[0]), "=r"(r[1]), "=r"(r[2]), "=r"(r[3]) : "r"(addr));
}

__device__ __forceinline__ uint32_t h2pack(float lo, float hi) {
    __half2 h = __floats2half2_rn(lo, hi);
    return *(uint32_t*)&h;
}

// ---------------------------------------------------------------------------
// FP16 tensor-core GEMM: C[M,N] = A[M,K] @ W[N,K]^T (fp16 in, f32 accum)
// 128x256x32 tiles, 256 threads (8 warps, 2m x 4n), warp tile 64x64.
// 3-stage cp.async, ldmatrix fragment loads, conflict-free stride 40.
// HOUT: write fp16 output, else fp32.
// ---------------------------------------------------------------------------
#define TBM 128
#define TBN 256
#define TBK 32
#define TSTH 40
#define ASZH (TBM * TSTH)                // 5120 halves
#define BSZH (TBN * TSTH)                // 10240 halves
#define NSTG 3
#define GEMM_SMEM (NSTG * (ASZH + BSZH) * 2)   // 92160 B

template<bool HOUT>
__global__ __launch_bounds__(256) void gemm_f16(
    const __half* __restrict__ A, const __half* __restrict__ W,
    float* __restrict__ C, __half* __restrict__ Ch, int M, int N, int K)
{
    extern __shared__ __half smem_h[];
    __half* SA = smem_h;
    __half* SB = smem_h + NSTG * ASZH;

    const int tid  = threadIdx.x;
    const int lane = tid & 31;
    const int wid  = tid >> 5;
    const int wm   = (wid & 1) * 64;     // warp m offset
    const int wn   = (wid >> 1) * 64;    // warp n offset (4 warps cover 256)
    const int g    = lane >> 2;
    const int t    = lane & 3;

    const int bm = blockIdx.y * TBM;
    const int bn = blockIdx.x * TBN;

    const uint32_t sa_base = (uint32_t)__cvta_generic_to_shared(SA);
    const uint32_t sb_base = (uint32_t)__cvta_generic_to_shared(SB);

    const int lrow = lane & 15;
    const int lcol = (lane >> 4) * 8;

    float acc[4][8][4];
#pragma unroll
    for (int mt = 0; mt < 4; mt++)
#pragma unroll
        for (int nt = 0; nt < 8; nt++)
#pragma unroll
            for (int i = 0; i < 4; i++) acc[mt][nt][i] = 0.f;

    const int nk = K / TBK;

    // Per-stage: A 128 rows x 4 units (512 cp), B 256 rows x 4 units (1024 cp)
    // = 1536 cp / 256 threads = 6 per thread.
    const int ar = tid >> 2;             // 0..63 (+64)
    const int uu = (tid & 3) * 8;        // 0..24 halves
    auto load_stage = [&](int kt) {
        const int s  = kt % NSTG;
        const int ke = kt * TBK;
#pragma unroll
        for (int i = 0; i < 2; i++) {
            int row = ar + 64 * i;
            cp16(sa_base + (s * ASZH + row * TSTH + uu) * 2,
                 A + (size_t)(bm + row) * K + ke + uu);
        }
#pragma unroll
        for (int i = 0; i < 4; i++) {
            int row = ar + 64 * i;
            cp16(sb_base + (s * BSZH + row * TSTH + uu) * 2,
                 W + (size_t)(bn + row) * K + ke + uu);
        }
    };

#pragma unroll
    for (int s = 0; s < NSTG - 1; s++) {
        load_stage(s);
        asm volatile("cp.async.commit_group;\n");
    }

    for (int kt = 0; kt < nk; kt++) {
        if (kt + NSTG - 1 < nk) load_stage(kt + NSTG - 1);
        asm volatile("cp.async.commit_group;\n");
        asm volatile("cp.async.wait_group %0;\n" :: "n"(NSTG - 1));
        __syncthreads();

        const int s = kt % NSTG;
#pragma unroll
        for (int ks = 0; ks < 2; ks++) {
            uint32_t af[4][4], bf[8][2];
#pragma unroll
            for (int mt = 0; mt < 4; mt++) {
                uint32_t addr = sa_base +
                    (s * ASZH + (wm + mt * 16 + lrow) * TSTH + ks * 16 + lcol) * 2;
                ldsm4(af[mt], addr);
            }
#pragma unroll
            for (int np = 0; np < 4; np++) {
                uint32_t bq[4];
                uint32_t addr = sb_base +
                    (s * BSZH + (wn + np * 16 + lrow) * TSTH + ks * 16 + lcol) * 2;
                ldsm4(bq, addr);
                bf[2 * np][0] = bq[0]; bf[2 * np][1] = bq[2];
                bf[2 * np + 1][0] = bq[1]; bf[2 * np + 1][1] = bq[3];
            }
#pragma unroll
            for (int mt = 0; mt < 4; mt++)
#pragma unroll
                for (int nt = 0; nt < 8; nt++)
                    mma_f16(acc[mt][nt], af[mt], bf[nt][0], bf[nt][1]);
        }
        __syncthreads();
    }

    if (HOUT) {
        __half* Cp = Ch + (size_t)(bm + wm + g) * N + bn + wn + 2 * t;
#pragma unroll
        for (int mt = 0; mt < 4; mt++) {
#pragma unroll
            for (int nt = 0; nt < 8; nt++) {
                uint32_t v0 = h2pack(acc[mt][nt][0], acc[mt][nt][1]);
                uint32_t v1 = h2pack(acc[mt][nt][2], acc[mt][nt][3]);
                *(uint32_t*)(Cp + (size_t)(mt * 16) * N + nt * 8) = v0;
                *(uint32_t*)(Cp + (size_t)(mt * 16 + 8) * N + nt * 8) = v1;
            }
        }
    } else {
        float* Cp = C + (size_t)(bm + wm + g) * N + bn + wn + 2 * t;
#pragma unroll
        for (int mt = 0; mt < 4; mt++) {
#pragma unroll
            for (int nt = 0; nt < 8; nt++) {
                float* p0 = Cp + (size_t)(mt * 16) * N + nt * 8;
                *(float2*)p0 = make_float2(acc[mt][nt][0], acc[mt][nt][1]);
                float* p1 = p0 + (size_t)8 * N;
                *(float2*)p1 = make_float2(acc[mt][nt][2], acc[mt][nt][3]);
            }
        }
    }
}

// ---------------------------------------------------------------------------
// FP16 tensor-core causal flash attention (reads fused QKV, stride 3072).
// q-tile 128 (8 warps x 16 rows), k-tile 64, d=64, double-buffered K/V.
// ---------------------------------------------------------------------------
#define AQ   128
#define KT_  64
#define AST  72
#define QSZ  (AQ * AST)
#define KVSZ (KT_ * AST)
#define ATTN_SMEM ((QSZ + 2 * 2 * KVSZ) * 2) // 55296 B

__global__ __launch_bounds__(256) void attn_mma(
    const __half* __restrict__ QKV, __half* __restrict__ O)
{
    extern __shared__ __half sm[];
    const uint32_t sbase = (uint32_t)__cvta_generic_to_shared(sm);
    const uint32_t qs = sbase;

    const int tid  = threadIdx.x;
    const int lane = tid & 31;
    const int ws   = tid >> 5;
    const int g    = lane >> 2;
    const int t    = lane & 3;
    const int lrow = lane & 15;
    const int lcol = (lane >> 4) * 8;

    const int bh = blockIdx.y;
    const int b  = bh >> 4;
    const int h  = bh & 15;
    const int qm = gridDim.x - 1 - blockIdx.x;
    const int q0 = qm * AQ;

    const __half* Qg = QKV + (size_t)b * S_ * LDQKV + (size_t)h * DK_;
    const __half* Kg = Qg + D_;
    const __half* Vg = Qg + 2 * D_;
    __half*       Og = O + (size_t)b * S_ * D_ + (size_t)h * DK_;

    auto load_kv = [&](int s, int kt) {
        const int k0 = kt * KT_;
#pragma unroll
        for (int i = 0; i < 2; i++) {
            int idx = tid + 256 * i;
            int row = idx >> 3;
            int u   = (idx & 7) * 8;
            uint32_t kdst = sbase + (QSZ + s * 2 * KVSZ + row * AST + u) * 2;
            cp16(kdst, Kg + (size_t)(k0 + row) * LDQKV + u);
            cp16(kdst + KVSZ * 2, Vg + (size_t)(k0 + row) * LDQKV + u);
        }
    };

#pragma unroll
    for (int i = 0; i < 4; i++) {
        int idx = tid + 256 * i;
        int row = idx >> 3;
        int u   = (idx & 7) * 8;
        cp16(qs + (row * AST + u) * 2, Qg + (size_t)(q0 + row) * LDQKV + u);
    }
    load_kv(0, 0);
    asm volatile("cp.async.commit_group;\n");
    asm volatile("cp.async.wait_group 0;\n");
    __syncthreads();

    uint32_t qf[4][4];
#pragma unroll
    for (int kc = 0; kc < 4; kc++)
        ldsm4(qf[kc], qs + ((ws * 16 + lrow) * AST + kc * 16 + lcol) * 2);

    float o[8][4];
#pragma unroll
    for (int nt = 0; nt < 8; nt++)
#pragma unroll
        for (int i = 0; i < 4; i++) o[nt][i] = 0.f;
    float mi0 = -1e30f, mi1 = -1e30f, li0 = 0.f, li1 = 0.f;

    const int last = q0 / 64 + 1;
    const float sc = 0.125f;
    const int qrow0 = q0 + ws * 16 + g;
    const int qrow1 = qrow0 + 8;

    for (int kt = 0; kt <= last; kt++) {
        const int k0 = kt * KT_;
        if (kt < last) {
            load_kv((kt + 1) & 1, kt + 1);
            asm volatile("cp.async.commit_group;\n");
        }
        if (kt > 0) {
            if (kt < last) asm volatile("cp.async.wait_group 1;\n");
            else           asm volatile("cp.async.wait_group 0;\n");
        }
        __syncthreads();

        const uint32_t ks_ = sbase + (QSZ + (kt & 1) * 2 * KVSZ) * 2;
        const uint32_t vs_ = ks_ + KVSZ * 2;

        float s[8][4];
#pragma unroll
        for (int nt = 0; nt < 8; nt++)
#pragma unroll
            for (int i = 0; i < 4; i++) s[nt][i] = 0.f;
#pragma unroll
        for (int kc = 0; kc < 4; kc++) {
#pragma unroll
            for (int np = 0; np < 4; np++) {
                uint32_t bq[4];
                ldsm4(bq, ks_ + ((np * 16 + lrow) * AST + kc * 16 + lcol) * 2);
                mma_f16(s[2 * np],     qf[kc], bq[0], bq[2]);
                mma_f16(s[2 * np + 1], qf[kc], bq[1], bq[3]);
            }
        }

        if (k0 >= q0) {
#pragma unroll
            for (int nt = 0; nt < 8; nt++) {
                int c0 = k0 + nt * 8 + 2 * t;
                s[nt][0] = (c0     <= qrow0) ? s[nt][0] * sc : -1e30f;
                s[nt][1] = (c0 + 1 <= qrow0) ? s[nt][1] * sc : -1e30f;
                s[nt][2] = (c0     <= qrow1) ? s[nt][2] * sc : -1e30f;
                s[nt][3] = (c0 + 1 <= qrow1) ? s[nt][3] * sc : -1e30f;
            }
        } else {
#pragma unroll
            for (int nt = 0; nt < 8; nt++)
#pragma unroll
                for (int i = 0; i < 4; i++) s[nt][i] *= sc;
        }

        float rm0 = -1e30f, rm1 = -1e30f;
#pragma unroll
        for (int nt = 0; nt < 8; nt++) {
            rm0 = fmaxf(rm0, fmaxf(s[nt][0], s[nt][1]));
            rm1 = fmaxf(rm1, fmaxf(s[nt][2], s[nt][3]));
        }
#pragma unroll
        for (int off = 1; off <= 2; off <<= 1) {
            rm0 = fmaxf(rm0, __shfl_xor_sync(0xffffffffu, rm0, off));
            rm1 = fmaxf(rm1, __shfl_xor_sync(0xffffffffu, rm1, off));
        }
        float mn0 = fmaxf(mi0, rm0), mn1 = fmaxf(mi1, rm1);
        float rs0 = 0.f, rs1 = 0.f;
#pragma unroll
        for (int nt = 0; nt < 8; nt++) {
            s[nt][0] = __expf(s[nt][0] - mn0);
            s[nt][1] = __expf(s[nt][1] - mn0);
            s[nt][2] = __expf(s[nt][2] - mn1);
            s[nt][3] = __expf(s[nt][3] - mn1);
            rs0 += s[nt][0] + s[nt][1];
            rs1 += s[nt][2] + s[nt][3];
        }
#pragma unroll
        for (int off = 1; off <= 2; off <<= 1) {
            rs0 += __shfl_xor_sync(0xffffffffu, rs0, off);
            rs1 += __shfl_xor_sync(0xffffffffu, rs1, off);
        }
        float al0 = __expf(mi0 - mn0), al1 = __expf(mi1 - mn1);
        li0 = li0 * al0 + rs0;  li1 = li1 * al1 + rs1;
        mi0 = mn0;  mi1 = mn1;
#pragma unroll
        for (int nt = 0; nt < 8; nt++) {
            o[nt][0] *= al0; o[nt][1] *= al0;
            o[nt][2] *= al1; o[nt][3] *= al1;
        }

        uint32_t pa[4][4];
#pragma unroll
        for (int kc = 0; kc < 4; kc++) {
            pa[kc][0] = h2pack(s[2 * kc][0],     s[2 * kc][1]);
            pa[kc][1] = h2pack(s[2 * kc][2],     s[2 * kc][3]);
            pa[kc][2] = h2pack(s[2 * kc + 1][0], s[2 * kc + 1][1]);
            pa[kc][3] = h2pack(s[2 * kc + 1][2], s[2 * kc + 1][3]);
        }

        const int trow = (lane & 7) + ((lane & 16) ? 8 : 0);
        const int tcol = (lane & 8) ? 8 : 0;
#pragma unroll
        for (int kc = 0; kc < 4; kc++) {
#pragma unroll
            for (int dp = 0; dp < 4; dp++) {
                uint32_t rv[4];
                ldsm4t(rv, vs_ + ((kc * 16 + trow) * AST + dp * 16 + tcol) * 2);
                mma_f16(o[2 * dp],     pa[kc], rv[0], rv[2]);
                mma_f16(o[2 * dp + 1], pa[kc], rv[1], rv[3]);
            }
        }
        __syncthreads();
    }

    const float iv0 = 1.0f / li0, iv1 = 1.0f / li1;
#pragma unroll
    for (int nt = 0; nt < 8; nt++) {
        int col = nt * 8 + 2 * t;
        uint32_t v0 = h2pack(o[nt][0] * iv0, o[nt][1] * iv0);
        uint32_t v1 = h2pack(o[nt][2] * iv1, o[nt][3] * iv1);
        *(uint32_t*)(Og + (size_t)qrow0 * D_ + col) = v0;
        *(uint32_t*)(Og + (size_t)qrow1 * D_ + col) = v1;
    }
}

// ---------------------------------------------------------------------------
// Launch
// ---------------------------------------------------------------------------
extern "C" void kernel_launch(void* const* d_in, const int* in_sizes, int n_in,
                              void* d_out, int out_size)
{
    const float* x  = (const float*)d_in[0];
    const float* WQ = (const float*)d_in[1];
    const float* WK = (const float*)d_in[2];
    const float* WV = (const float*)d_in[3];
    const float* WO = (const float*)d_in[4];
    float* out = (float*)d_out;

    __half *Xh, *Wh, *QKVh, *Ah;
    cudaGetSymbolAddress((void**)&Xh, g_Xh);
    cudaGetSymbolAddress((void**)&Wh, g_Wh);
    cudaGetSymbolAddress((void**)&QKVh, g_QKVh);
    cudaGetSymbolAddress((void**)&Ah, g_Ah);

    cudaFuncSetAttribute(gemm_f16<true>,
                         cudaFuncAttributeMaxDynamicSharedMemorySize, GEMM_SMEM);
    cudaFuncSetAttribute(gemm_f16<false>,
                         cudaFuncAttributeMaxDynamicSharedMemorySize, GEMM_SMEM);
    cudaFuncSetAttribute(attn_mma,
                         cudaFuncAttributeMaxDynamicSharedMemorySize, ATTN_SMEM);

    const int M   = B_ * S_;
    const int nX8 = (M * D_) / 8;
    const int nW8 = (D_ * D_) / 8;

    cvt_f16_k<<<(nX8 + 255) / 256, 256>>>((const float4*)x, (uint4*)Xh, nX8);
    cvt_f16_k<<<(nW8 + 255) / 256, 256>>>((const float4*)WQ, (uint4*)(Wh + 0 * (size_t)D_ * D_), nW8);
    cvt_f16_k<<<(nW8 + 255) / 256, 256>>>((const float4*)WK, (uint4*)(Wh + 1 * (size_t)D_ * D_), nW8);
    cvt_f16_k<<<(nW8 + 255) / 256, 256>>>((const float4*)WV, (uint4*)(Wh + 2 * (size_t)D_ * D_), nW8);
    cvt_f16_k<<<(nW8 + 255) / 256, 256>>>((const float4*)WO, (uint4*)(Wh + 3 * (size_t)D_ * D_), nW8);

    // Fused QKV projection: one launch, N = 3072
    dim3 gq(LDQKV / TBN, M / TBM);                 // (12, 64)
    gemm_f16<true><<<gq, 256, GEMM_SMEM>>>(Xh, Wh, nullptr, QKVh, M, LDQKV, D_);

    attn_mma<<<dim3(S_ / AQ, B_ * H_), 256, ATTN_SMEM>>>(QKVh, Ah);

    // Output projection
    dim3 go(D_ / TBN, M / TBM);                    // (4, 64)
    gemm_f16<false><<<go, 256, GEMM_SMEM>>>(Ah, Wh + 3 * (size_t)D_ * D_, out, nullptr, M, D_, D_);
}

// round 15
// speedup vs baseline: 1.0698x; 1.0698x over previous
#include <cuda_runtime.h>
#include <cuda_fp16.h>
#include <math.h>
#include <stdint.h>

#define B_  4
#define S_  2048
#define D_  1024
#define H_  16
#define DK_ 64
#define LDQKV 3072                           // row stride of fused QKV output

// fp16 scratch (allocation-free rule: __device__ globals)
__device__ __half g_Xh[(size_t)B_ * S_ * D_];
__device__ __half g_Wh[(size_t)4 * D_ * D_];   // WQ|WK|WV|WO contiguous
__device__ __half g_QKVh[(size_t)B_ * S_ * LDQKV];
__device__ __half g_Ah[(size_t)B_ * S_ * D_];

// ---------------------------------------------------------------------------
// fp32 -> fp16 converts
// ---------------------------------------------------------------------------
__global__ void cvt_f16_k(const float4* __restrict__ in,
                          uint4* __restrict__ out, int n8)
{
    int i = blockIdx.x * blockDim.x + threadIdx.x;
    if (i < n8) {
        float4 a = in[2 * i];
        float4 b = in[2 * i + 1];
        __half2 h0 = __floats2half2_rn(a.x, a.y);
        __half2 h1 = __floats2half2_rn(a.z, a.w);
        __half2 h2 = __floats2half2_rn(b.x, b.y);
        __half2 h3 = __floats2half2_rn(b.z, b.w);
        uint4 u;
        u.x = *(uint32_t*)&h0; u.y = *(uint32_t*)&h1;
        u.z = *(uint32_t*)&h2; u.w = *(uint32_t*)&h3;
        out[i] = u;
    }
}

// All 4 weights in one launch: block range selects source pointer.
__global__ void cvt_w4_k(const float4* __restrict__ w0,
                         const float4* __restrict__ w1,
                         const float4* __restrict__ w2,
                         const float4* __restrict__ w3,
                         uint4* __restrict__ out, int n8_per)
{
    int gi = blockIdx.x * blockDim.x + threadIdx.x;
    int w  = gi / n8_per;
    int i  = gi - w * n8_per;
    if (w >= 4) return;
    const float4* in = (w == 0) ? w0 : (w == 1) ? w1 : (w == 2) ? w2 : w3;
    float4 a = in[2 * i];
    float4 b = in[2 * i + 1];
    __half2 h0 = __floats2half2_rn(a.x, a.y);
    __half2 h1 = __floats2half2_rn(a.z, a.w);
    __half2 h2 = __floats2half2_rn(b.x, b.y);
    __half2 h3 = __floats2half2_rn(b.z, b.w);
    uint4 u;
    u.x = *(uint32_t*)&h0; u.y = *(uint32_t*)&h1;
    u.z = *(uint32_t*)&h2; u.w = *(uint32_t*)&h3;
    out[(size_t)w * n8_per + i] = u;
}

// ---------------------------------------------------------------------------
// mma / ldmatrix helpers
// ---------------------------------------------------------------------------
__device__ __forceinline__ void cp16(uint32_t dst_smem, const void* src) {
    asm volatile("cp.async.cg.shared.global [%0], [%1], 16;\n"
                 :: "r"(dst_smem), "l"(src));
}

__device__ __forceinline__ void mma_f16(float c[4], const uint32_t a[4],
                                        uint32_t b0, uint32_t b1) {
    asm volatile(
        "mma.sync.aligned.m16n8k16.row.col.f32.f16.f16.f32 "
        "{%0,%1,%2,%3}, {%4,%5,%6,%7}, {%8,%9}, {%0,%1,%2,%3};\n"
        : "+f"(c[0]), "+f"(c[1]), "+f"(c[2]), "+f"(c[3])
        : "r"(a[0]), "r"(a[1]), "r"(a[2]), "r"(a[3]), "r"(b0), "r"(b1));
}

__device__ __forceinline__ void ldsm4(uint32_t* r, uint32_t addr) {
    asm volatile("ldmatrix.sync.aligned.m8n8.x4.shared.b16 "
                 "{%0,%1,%2,%3}, [%4];"
                 : "=r"(r[0]), "=r"(r[1]), "=r"(r[2]), "=r"(r[3]) : "r"(addr));
}

__device__ __forceinline__ void ldsm4t(uint32_t* r, uint32_t addr) {
    asm volatile("ldmatrix.sync.aligned.m8n8.x4.trans.shared.b16 "
                 "{%0,%1,%2,%3}, [%4];"
                 : "=r"(r[0]), "=r"(r[1]), "=r"(r[2]), "=r"(r[3]) : "r"(addr));
}

__device__ __forceinline__ uint32_t h2pack(float lo, float hi) {
    __half2 h = __floats2half2_rn(lo, hi);
    return *(uint32_t*)&h;
}

// ---------------------------------------------------------------------------
// FP16 tensor-core GEMM (R13 proven config): C[M,N] = A[M,K] @ W[N,K]^T
// 128x128x32 tiles, 256 threads, warp tile 64x32, 4-stage cp.async,
// ldmatrix fragment loads, conflict-free stride 40. 2 CTAs/SM.
// ---------------------------------------------------------------------------
#define TBM 128
#define TBN 128
#define TBK 32
#define TSTH 40
#define ASZH (TBM * TSTH)
#define BSZH (TBN * TSTH)
#define NSTG 4
#define GEMM_SMEM (NSTG * (ASZH + BSZH) * 2)   // 81920 B

template<bool HOUT>
__global__ __launch_bounds__(256) void gemm_f16(
    const __half* __restrict__ A, const __half* __restrict__ W,
    float* __restrict__ C, __half* __restrict__ Ch, int M, int N, int K)
{
    extern __shared__ __half smem_h[];
    __half* SA = smem_h;
    __half* SB = smem_h + NSTG * ASZH;

    const int tid  = threadIdx.x;
    const int lane = tid & 31;
    const int wid  = tid >> 5;
    const int wm   = (wid & 1) * 64;
    const int wn   = (wid >> 1) * 32;
    const int g    = lane >> 2;
    const int t    = lane & 3;

    const int bm = blockIdx.y * TBM;
    const int bn = blockIdx.x * TBN;

    const uint32_t sa_base = (uint32_t)__cvta_generic_to_shared(SA);
    const uint32_t sb_base = (uint32_t)__cvta_generic_to_shared(SB);

    const int r0 = tid >> 2;
    const int u0 = (tid & 3) * 8;

    const int lrow = lane & 15;
    const int lcol = (lane >> 4) * 8;

    float acc[4][4][4];
#pragma unroll
    for (int mt = 0; mt < 4; mt++)
#pragma unroll
        for (int nt = 0; nt < 4; nt++)
#pragma unroll
            for (int i = 0; i < 4; i++) acc[mt][nt][i] = 0.f;

    const int nk = K / TBK;

    auto load_stage = [&](int kt) {
        const int s  = kt % NSTG;
        const int ke = kt * TBK;
#pragma unroll
        for (int i = 0; i < 2; i++) {
            int row = r0 + 64 * i;
            cp16(sa_base + (s * ASZH + row * TSTH + u0) * 2,
                 A + (size_t)(bm + row) * K + ke + u0);
            cp16(sb_base + (s * BSZH + row * TSTH + u0) * 2,
                 W + (size_t)(bn + row) * K + ke + u0);
        }
    };

#pragma unroll
    for (int s = 0; s < NSTG - 1; s++) {
        load_stage(s);
        asm volatile("cp.async.commit_group;\n");
    }

    for (int kt = 0; kt < nk; kt++) {
        if (kt + NSTG - 1 < nk) load_stage(kt + NSTG - 1);
        asm volatile("cp.async.commit_group;\n");
        asm volatile("cp.async.wait_group %0;\n" :: "n"(NSTG - 1));
        __syncthreads();

        const int s = kt % NSTG;
#pragma unroll
        for (int ks = 0; ks < 2; ks++) {
            uint32_t af[4][4], bf[4][2];
#pragma unroll
            for (int mt = 0; mt < 4; mt++) {
                uint32_t addr = sa_base +
                    (s * ASZH + (wm + mt * 16 + lrow) * TSTH + ks * 16 + lcol) * 2;
                ldsm4(af[mt], addr);
            }
#pragma unroll
            for (int np = 0; np < 2; np++) {
                uint32_t bq[4];
                uint32_t addr = sb_base +
                    (s * BSZH + (wn + np * 16 + lrow) * TSTH + ks * 16 + lcol) * 2;
                ldsm4(bq, addr);
                bf[2 * np][0] = bq[0]; bf[2 * np][1] = bq[2];
                bf[2 * np + 1][0] = bq[1]; bf[2 * np + 1][1] = bq[3];
            }
#pragma unroll
            for (int mt = 0; mt < 4; mt++)
#pragma unroll
                for (int nt = 0; nt < 4; nt++)
                    mma_f16(acc[mt][nt], af[mt], bf[nt][0], bf[nt][1]);
        }
        __syncthreads();
    }

    if (HOUT) {
        __half* Cp = Ch + (size_t)(bm + wm + g) * N + bn + wn + 2 * t;
#pragma unroll
        for (int mt = 0; mt < 4; mt++) {
#pragma unroll
            for (int nt = 0; nt < 4; nt++) {
                uint32_t v0 = h2pack(acc[mt][nt][0], acc[mt][nt][1]);
                uint32_t v1 = h2pack(acc[mt][nt][2], acc[mt][nt][3]);
                *(uint32_t*)(Cp + (size_t)(mt * 16) * N + nt * 8) = v0;
                *(uint32_t*)(Cp + (size_t)(mt * 16 + 8) * N + nt * 8) = v1;
            }
        }
    } else {
        float* Cp = C + (size_t)(bm + wm + g) * N + bn + wn + 2 * t;
#pragma unroll
        for (int mt = 0; mt < 4; mt++) {
#pragma unroll
            for (int nt = 0; nt < 4; nt++) {
                float* p0 = Cp + (size_t)(mt * 16) * N + nt * 8;
                *(float2*)p0 = make_float2(acc[mt][nt][0], acc[mt][nt][1]);
                float* p1 = p0 + (size_t)8 * N;
                *(float2*)p1 = make_float2(acc[mt][nt][2], acc[mt][nt][3]);
            }
        }
    }
}

// ---------------------------------------------------------------------------
// FP16 tensor-core causal flash attention (reads fused QKV, stride 3072).
// q-tile 128 (8 warps x 16 rows), k-tile 64, d=64, double-buffered K/V.
// ---------------------------------------------------------------------------
#define AQ   128
#define KT_  64
#define AST  72
#define QSZ  (AQ * AST)
#define KVSZ (KT_ * AST)
#define ATTN_SMEM ((QSZ + 2 * 2 * KVSZ) * 2) // 55296 B

__global__ __launch_bounds__(256) void attn_mma(
    const __half* __restrict__ QKV, __half* __restrict__ O)
{
    extern __shared__ __half sm[];
    const uint32_t sbase = (uint32_t)__cvta_generic_to_shared(sm);
    const uint32_t qs = sbase;

    const int tid  = threadIdx.x;
    const int lane = tid & 31;
    const int ws   = tid >> 5;
    const int g    = lane >> 2;
    const int t    = lane & 3;
    const int lrow = lane & 15;
    const int lcol = (lane >> 4) * 8;

    const int bh = blockIdx.y;
    const int b  = bh >> 4;
    const int h  = bh & 15;
    const int qm = gridDim.x - 1 - blockIdx.x;
    const int q0 = qm * AQ;

    const __half* Qg = QKV + (size_t)b * S_ * LDQKV + (size_t)h * DK_;
    const __half* Kg = Qg + D_;
    const __half* Vg = Qg + 2 * D_;
    __half*       Og = O + (size_t)b * S_ * D_ + (size_t)h * DK_;

    auto load_kv = [&](int s, int kt) {
        const int k0 = kt * KT_;
#pragma unroll
        for (int i = 0; i < 2; i++) {
            int idx = tid + 256 * i;
            int row = idx >> 3;
            int u   = (idx & 7) * 8;
            uint32_t kdst = sbase + (QSZ + s * 2 * KVSZ + row * AST + u) * 2;
            cp16(kdst, Kg + (size_t)(k0 + row) * LDQKV + u);
            cp16(kdst + KVSZ * 2, Vg + (size_t)(k0 + row) * LDQKV + u);
        }
    };

#pragma unroll
    for (int i = 0; i < 4; i++) {
        int idx = tid + 256 * i;
        int row = idx >> 3;
        int u   = (idx & 7) * 8;
        cp16(qs + (row * AST + u) * 2, Qg + (size_t)(q0 + row) * LDQKV + u);
    }
    load_kv(0, 0);
    asm volatile("cp.async.commit_group;\n");
    asm volatile("cp.async.wait_group 0;\n");
    __syncthreads();

    uint32_t qf[4][4];
#pragma unroll
    for (int kc = 0; kc < 4; kc++)
        ldsm4(qf[kc], qs + ((ws * 16 + lrow) * AST + kc * 16 + lcol) * 2);

    float o[8][4];
#pragma unroll
    for (int nt = 0; nt < 8; nt++)
#pragma unroll
        for (int i = 0; i < 4; i++) o[nt][i] = 0.f;
    float mi0 = -1e30f, mi1 = -1e30f, li0 = 0.f, li1 = 0.f;

    const int last = q0 / 64 + 1;
    const float sc = 0.125f;
    const int qrow0 = q0 + ws * 16 + g;
    const int qrow1 = qrow0 + 8;

    for (int kt = 0; kt <= last; kt++) {
        const int k0 = kt * KT_;
        if (kt < last) {
            load_kv((kt + 1) & 1, kt + 1);
            asm volatile("cp.async.commit_group;\n");
        }
        if (kt > 0) {
            if (kt < last) asm volatile("cp.async.wait_group 1;\n");
            else           asm volatile("cp.async.wait_group 0;\n");
        }
        __syncthreads();

        const uint32_t ks_ = sbase + (QSZ + (kt & 1) * 2 * KVSZ) * 2;
        const uint32_t vs_ = ks_ + KVSZ * 2;

        float s[8][4];
#pragma unroll
        for (int nt = 0; nt < 8; nt++)
#pragma unroll
            for (int i = 0; i < 4; i++) s[nt][i] = 0.f;
#pragma unroll
        for (int kc = 0; kc < 4; kc++) {
#pragma unroll
            for (int np = 0; np < 4; np++) {
                uint32_t bq[4];
                ldsm4(bq, ks_ + ((np * 16 + lrow) * AST + kc * 16 + lcol) * 2);
                mma_f16(s[2 * np],     qf[kc], bq[0], bq[2]);
                mma_f16(s[2 * np + 1], qf[kc], bq[1], bq[3]);
            }
        }

        if (k0 >= q0) {
#pragma unroll
            for (int nt = 0; nt < 8; nt++) {
                int c0 = k0 + nt * 8 + 2 * t;
                s[nt][0] = (c0     <= qrow0) ? s[nt][0] * sc : -1e30f;
                s[nt][1] = (c0 + 1 <= qrow0) ? s[nt][1] * sc : -1e30f;
                s[nt][2] = (c0     <= qrow1) ? s[nt][2] * sc : -1e30f;
                s[nt][3] = (c0 + 1 <= qrow1) ? s[nt][3] * sc : -1e30f;
            }
        } else {
#pragma unroll
            for (int nt = 0; nt < 8; nt++)
#pragma unroll
                for (int i = 0; i < 4; i++) s[nt][i] *= sc;
        }

        float rm0 = -1e30f, rm1 = -1e30f;
#pragma unroll
        for (int nt = 0; nt < 8; nt++) {
            rm0 = fmaxf(rm0, fmaxf(s[nt][0], s[nt][1]));
            rm1 = fmaxf(rm1, fmaxf(s[nt][2], s[nt][3]));
        }
#pragma unroll
        for (int off = 1; off <= 2; off <<= 1) {
            rm0 = fmaxf(rm0, __shfl_xor_sync(0xffffffffu, rm0, off));
            rm1 = fmaxf(rm1, __shfl_xor_sync(0xffffffffu, rm1, off));
        }
        float mn0 = fmaxf(mi0, rm0), mn1 = fmaxf(mi1, rm1);
        float rs0 = 0.f, rs1 = 0.f;
#pragma unroll
        for (int nt = 0; nt < 8; nt++) {
            s[nt][0] = __expf(s[nt][0] - mn0);
            s[nt][1] = __expf(s[nt][1] - mn0);
            s[nt][2] = __expf(s[nt][2] - mn1);
            s[nt][3] = __expf(s[nt][3] - mn1);
            rs0 += s[nt][0] + s[nt][1];
            rs1 += s[nt][2] + s[nt][3];
        }
#pragma unroll
        for (int off = 1; off <= 2; off <<= 1) {
            rs0 += __shfl_xor_sync(0xffffffffu, rs0, off);
            rs1 += __shfl_xor_sync(0xffffffffu, rs1, off);
        }
        float al0 = __expf(mi0 - mn0), al1 = __expf(mi1 - mn1);
        li0 = li0 * al0 + rs0;  li1 = li1 * al1 + rs1;
        mi0 = mn0;  mi1 = mn1;
#pragma unroll
        for (int nt = 0; nt < 8; nt++) {
            o[nt][0] *= al0; o[nt][1] *= al0;
            o[nt][2] *= al1; o[nt][3] *= al1;
        }

        uint32_t pa[4][4];
#pragma unroll
        for (int kc = 0; kc < 4; kc++) {
            pa[kc][0] = h2pack(s[2 * kc][0],     s[2 * kc][1]);
            pa[kc][1] = h2pack(s[2 * kc][2],     s[2 * kc][3]);
            pa[kc][2] = h2pack(s[2 * kc + 1][0], s[2 * kc + 1][1]);
            pa[kc][3] = h2pack(s[2 * kc + 1][2], s[2 * kc + 1][3]);
        }

        const int trow = (lane & 7) + ((lane & 16) ? 8 : 0);
        const int tcol = (lane & 8) ? 8 : 0;
#pragma unroll
        for (int kc = 0; kc < 4; kc++) {
#pragma unroll
            for (int dp = 0; dp < 4; dp++) {
                uint32_t rv[4];
                ldsm4t(rv, vs_ + ((kc * 16 + trow) * AST + dp * 16 + tcol) * 2);
                mma_f16(o[2 * dp],     pa[kc], rv[0], rv[2]);
                mma_f16(o[2 * dp + 1], pa[kc], rv[1], rv[3]);
            }
        }
        __syncthreads();
    }

    const float iv0 = 1.0f / li0, iv1 = 1.0f / li1;
#pragma unroll
    for (int nt = 0; nt < 8; nt++) {
        int col = nt * 8 + 2 * t;
        uint32_t v0 = h2pack(o[nt][0] * iv0, o[nt][1] * iv0);
        uint32_t v1 = h2pack(o[nt][2] * iv1, o[nt][3] * iv1);
        *(uint32_t*)(Og + (size_t)qrow0 * D_ + col) = v0;
        *(uint32_t*)(Og + (size_t)qrow1 * D_ + col) = v1;
    }
}

// ---------------------------------------------------------------------------
// Launch
// ---------------------------------------------------------------------------
extern "C" void kernel_launch(void* const* d_in, const int* in_sizes, int n_in,
                              void* d_out, int out_size)
{
    const float* x  = (const float*)d_in[0];
    const float* WQ = (const float*)d_in[1];
    const float* WK = (const float*)d_in[2];
    const float* WV = (const float*)d_in[3];
    const float* WO = (const float*)d_in[4];
    float* out = (float*)d_out;

    __half *Xh, *Wh, *QKVh, *Ah;
    cudaGetSymbolAddress((void**)&Xh, g_Xh);
    cudaGetSymbolAddress((void**)&Wh, g_Wh);
    cudaGetSymbolAddress((void**)&QKVh, g_QKVh);
    cudaGetSymbolAddress((void**)&Ah, g_Ah);

    cudaFuncSetAttribute(gemm_f16<true>,
                         cudaFuncAttributeMaxDynamicSharedMemorySize, GEMM_SMEM);
    cudaFuncSetAttribute(gemm_f16<false>,
                         cudaFuncAttributeMaxDynamicSharedMemorySize, GEMM_SMEM);
    cudaFuncSetAttribute(attn_mma,
                         cudaFuncAttributeMaxDynamicSharedMemorySize, ATTN_SMEM);

    const int M   = B_ * S_;
    const int nX8 = (M * D_) / 8;                  // 1,048,576
    const int nW8 = (D_ * D_) / 8;                 // 131,072

    // 2 cvt launches total: x, then all 4 weights fused
    cvt_f16_k<<<(nX8 + 255) / 256, 256>>>((const float4*)x, (uint4*)Xh, nX8);
    cvt_w4_k<<<(4 * nW8 + 255) / 256, 256>>>(
        (const float4*)WQ, (const float4*)WK, (const float4*)WV,
        (const float4*)WO, (uint4*)Wh, nW8);

    // Fused QKV projection: one launch, N = 3072, proven 128x128 tiles
    dim3 gq(LDQKV / TBN, M / TBM);                 // (24, 64)
    gemm_f16<true><<<gq, 256, GEMM_SMEM>>>(Xh, Wh, nullptr, QKVh, M, LDQKV, D_);

    attn_mma<<<dim3(S_ / AQ, B_ * H_), 256, ATTN_SMEM>>>(QKVh, Ah);

    // Output projection
    dim3 go(D_ / TBN, M / TBM);                    // (8, 64)
    gemm_f16<false><<<go, 256, GEMM_SMEM>>>(Ah, Wh + 3 * (size_t)D_ * D_, out, nullptr, M, D_, D_);
}